// round 10
// baseline (speedup 1.0000x reference)
#include <cuda_runtime.h>
#include <cuda_bf16.h>
#include <cstdint>
#include <cstddef>

#define NN 65536
#define DD 512
#define KK 256
#define OO 512
#define DEG 8
#define NTHR 512          // GEMM kernels
#define STHR 256          // split kernel

// ---------------- device-global scratch (allocation-free) ----------------
__device__ uint16_t g_z_hi[(size_t)NN * DD];          // 64 MB
__device__ uint16_t g_z_lo[(size_t)NN * DD];          // 64 MB
__device__ uint16_t g_T_hi[(size_t)DEG * KK * DD];    // 2 MB
__device__ uint16_t g_T_lo[(size_t)DEG * KK * DD];    // 2 MB
__device__ uint16_t g_Cw_hi[(size_t)OO * KK];         // 256 KB
__device__ uint16_t g_Cw_lo[(size_t)OO * KK];         // 256 KB
__device__ uint16_t g_o8_hi[(size_t)NN * KK];         // 32 MB
__device__ uint16_t g_o8_lo[(size_t)NN * KK];         // 32 MB

// ---------------- PTX helpers (sm_80-era only: valid on plain sm_103) ----
__device__ __forceinline__ uint32_t smem_u32(const void* p) {
    uint32_t a;
    asm("{ .reg .u64 t; cvta.to.shared.u64 t, %1; cvt.u32.u64 %0, t; }" : "=r"(a) : "l"(p));
    return a;
}
__device__ __forceinline__ void cp16(uint32_t dst, const void* src) {
    asm volatile("cp.async.cg.shared.global [%0], [%1], 16;" :: "r"(dst), "l"(src));
}
__device__ __forceinline__ void cp_commit() {
    asm volatile("cp.async.commit_group;" ::: "memory");
}
template <int N>
__device__ __forceinline__ void cp_wait() {
    asm volatile("cp.async.wait_group %0;" :: "n"(N) : "memory");
}
__device__ __forceinline__ void ldsm4(uint32_t* r, uint32_t addr) {
    asm volatile("ldmatrix.sync.aligned.m8n8.x4.shared.b16 {%0,%1,%2,%3}, [%4];"
                 : "=r"(r[0]), "=r"(r[1]), "=r"(r[2]), "=r"(r[3]) : "r"(addr));
}
__device__ __forceinline__ void mma_bf16(float* c, const uint32_t* a, uint32_t b0, uint32_t b1) {
    asm volatile(
        "mma.sync.aligned.m16n8k16.row.col.f32.bf16.bf16.f32 "
        "{%0,%1,%2,%3}, {%4,%5,%6,%7}, {%8,%9}, {%0,%1,%2,%3};"
        : "+f"(c[0]), "+f"(c[1]), "+f"(c[2]), "+f"(c[3])
        : "r"(a[0]), "r"(a[1]), "r"(a[2]), "r"(a[3]), "r"(b0), "r"(b1));
}
__device__ __forceinline__ uint32_t swz(uint32_t off) { return off ^ ((off >> 3) & 0x70); }

__device__ __forceinline__ uint16_t f2bf_bits(float x) {
    return __bfloat16_as_ushort(__float2bfloat16(x));
}
__device__ __forceinline__ float bf2f(uint16_t b) {
    return __bfloat162float(__ushort_as_bfloat16(b));
}

// load [ROWS x 64] bf16 tile -> SW128-swizzled smem (128B rows)
template <int ROWS, int THREADS>
__device__ __forceinline__ void load_tile(uint32_t smem_base, const uint16_t* src,
                                          size_t row_stride, int tid) {
    #pragma unroll 4
    for (int s = tid; s < ROWS * 8; s += THREADS) {
        int row = s >> 3, seg = s & 7;
        uint32_t off = (uint32_t)row * 128 + seg * 16;
        cp16(smem_base + swz(off), src + (size_t)row * row_stride + seg * 8);
    }
}

// ---------------------------------------------------------------------------
// split kernel: fp32 -> (hi, lo) bf16 pairs for z, T, Cw
// ---------------------------------------------------------------------------
__global__ void split_kernel(const float* __restrict__ z, const float* __restrict__ T,
                             const float* __restrict__ Cw) {
    const size_t gth = (size_t)blockIdx.x * blockDim.x + threadIdx.x;
    const size_t nth = (size_t)gridDim.x * blockDim.x;

    auto do_range = [&](const float* src, uint16_t* hi, uint16_t* lo, size_t n4) {
        for (size_t i = gth; i < n4; i += nth) {
            float4 v = ((const float4*)src)[i];
            uint16_t h0 = f2bf_bits(v.x), h1 = f2bf_bits(v.y);
            uint16_t h2 = f2bf_bits(v.z), h3 = f2bf_bits(v.w);
            uint16_t l0 = f2bf_bits(v.x - bf2f(h0));
            uint16_t l1 = f2bf_bits(v.y - bf2f(h1));
            uint16_t l2 = f2bf_bits(v.z - bf2f(h2));
            uint16_t l3 = f2bf_bits(v.w - bf2f(h3));
            ((uint2*)hi)[i] = make_uint2((uint32_t)h0 | ((uint32_t)h1 << 16),
                                         (uint32_t)h2 | ((uint32_t)h3 << 16));
            ((uint2*)lo)[i] = make_uint2((uint32_t)l0 | ((uint32_t)l1 << 16),
                                         (uint32_t)l2 | ((uint32_t)l3 << 16));
        }
    };
    do_range(z,  g_z_hi,  g_z_lo,  (size_t)NN * DD / 4);
    do_range(T,  g_T_hi,  g_T_lo,  (size_t)DEG * KK * DD / 4);
    do_range(Cw, g_Cw_hi, g_Cw_lo, (size_t)OO * KK / 4);
}

// ---------------------------------------------------------------------------
// Shared MMA-core: one chunk = [128 x 64] A x [128 x 64] B^T -> accumulate.
// Stage layout (64 KB): A_HI 0, A_LO 16K, B_HI 32K, B_LO 48K.
// 16 warps: wr = (wid&3)*32, wc = (wid>>2)*32 -> warp tile 32x32.
// acc[2][4][4]: m-tile(16), n-tile(8), frag.
// ---------------------------------------------------------------------------
#define ST_AH 0
#define ST_AL 16384
#define ST_BH 32768
#define ST_BL 49152
#define ST_BYTES 65536

__device__ __forceinline__ void compute_chunk(uint32_t st, float acc[2][4][4],
                                              int wr, int wc, int lane) {
    const int l15 = lane & 15;
    const int lk  = (lane >> 4) << 4;      // 0 or 16 bytes
    #pragma unroll
    for (int ks = 0; ks < 4; ks++) {
        const uint32_t kb = ks * 32 + lk;
        uint32_t ah[2][4], al[2][4], bh[2][4], bl[2][4];
        #pragma unroll
        for (int mt = 0; mt < 2; mt++)
            ldsm4(ah[mt], st + ST_AH + swz((uint32_t)(wr + mt * 16 + l15) * 128 + kb));
        #pragma unroll
        for (int ng = 0; ng < 2; ng++)
            ldsm4(bh[ng], st + ST_BH + swz((uint32_t)(wc + ng * 16 + l15) * 128 + kb));
        // hi * hi
        #pragma unroll
        for (int mt = 0; mt < 2; mt++)
            #pragma unroll
            for (int ng = 0; ng < 2; ng++) {
                mma_bf16(acc[mt][2 * ng],     ah[mt], bh[ng][0], bh[ng][2]);
                mma_bf16(acc[mt][2 * ng + 1], ah[mt], bh[ng][1], bh[ng][3]);
            }
        #pragma unroll
        for (int mt = 0; mt < 2; mt++)
            ldsm4(al[mt], st + ST_AL + swz((uint32_t)(wr + mt * 16 + l15) * 128 + kb));
        // lo * hi
        #pragma unroll
        for (int mt = 0; mt < 2; mt++)
            #pragma unroll
            for (int ng = 0; ng < 2; ng++) {
                mma_bf16(acc[mt][2 * ng],     al[mt], bh[ng][0], bh[ng][2]);
                mma_bf16(acc[mt][2 * ng + 1], al[mt], bh[ng][1], bh[ng][3]);
            }
        #pragma unroll
        for (int ng = 0; ng < 2; ng++)
            ldsm4(bl[ng], st + ST_BL + swz((uint32_t)(wc + ng * 16 + l15) * 128 + kb));
        // hi * lo
        #pragma unroll
        for (int mt = 0; mt < 2; mt++)
            #pragma unroll
            for (int ng = 0; ng < 2; ng++) {
                mma_bf16(acc[mt][2 * ng],     ah[mt], bl[ng][0], bl[ng][2]);
                mma_bf16(acc[mt][2 * ng + 1], ah[mt], bl[ng][1], bl[ng][3]);
            }
    }
}

// ---------------------------------------------------------------------------
// poly kernel: fused Legendre recurrence.
// CTA: 128 rows x 128 K-cols, 512 threads. G, prev1 in regs; prev2 in smem.
// ---------------------------------------------------------------------------
#define P2_OFF  (2 * ST_BYTES)                       // 131072
#define P2_PITCH 132
#define P_SMEM  (P2_OFF + 128 * P2_PITCH * 4)        // 198656

__global__ void __launch_bounds__(NTHR, 1)
poly_mma_kernel(const float* __restrict__ T0) {
    extern __shared__ char smem[];
    const uint32_t sbase = smem_u32(smem);
    float* prev2 = (float*)(smem + P2_OFF);

    const int tid  = threadIdx.x;
    const int lane = tid & 31;
    const int wid  = tid >> 5;
    const int wr   = (wid & 3) * 32;   // warp row base
    const int wc   = (wid >> 2) * 32;  // warp col base
    const int k0   = blockIdx.x * 128;
    const int row0 = blockIdx.y * 128;

    // prev2 init = T0[k] broadcast over rows (degree 0)
    for (int i = tid; i < 128 * 128; i += NTHR) {
        int r = i >> 7, c = i & 127;
        prev2[r * P2_PITCH + c] = __ldg(&T0[k0 + c]);
    }
    __syncthreads();

    float acc[2][4][4];
    float p1[2][4][4];

    auto prefetch = [&](int stage, int n1, int j1) {
        const uint32_t st = sbase + stage * ST_BYTES;
        const int d0 = j1 * 64;
        const uint16_t* Th = g_T_hi + (size_t)(n1 - 1) * KK * DD + (size_t)k0 * DD + d0;
        const uint16_t* Tl = g_T_lo + (size_t)(n1 - 1) * KK * DD + (size_t)k0 * DD + d0;
        load_tile<128, NTHR>(st + ST_AH, g_z_hi + (size_t)row0 * DD + d0, DD, tid);
        load_tile<128, NTHR>(st + ST_AL, g_z_lo + (size_t)row0 * DD + d0, DD, tid);
        load_tile<128, NTHR>(st + ST_BH, Th, DD, tid);
        load_tile<128, NTHR>(st + ST_BL, Tl, DD, tid);
        cp_commit();
    };

    prefetch(0, 1, 0);
    int it = 0;

    for (int n = 1; n <= DEG; n++) {
        #pragma unroll
        for (int mt = 0; mt < 2; mt++)
            #pragma unroll
            for (int nt = 0; nt < 4; nt++)
                #pragma unroll
                for (int f = 0; f < 4; f++) acc[mt][nt][f] = 0.0f;

        for (int j = 0; j < 8; j++) {
            const bool has_next = !(n == DEG && j == 7);
            if (has_next) {
                int j1 = j + 1, n1 = n;
                if (j1 == 8) { j1 = 0; n1 = n + 1; }
                prefetch((it + 1) & 1, n1, j1);
                cp_wait<1>();
            } else {
                cp_wait<0>();
            }
            __syncthreads();
            compute_chunk(sbase + (it & 1) * ST_BYTES, acc, wr, wc, lane);
            __syncthreads();
            it++;
        }

        // ---- recurrence epilogue for degree n ----
        const float fa = (2.0f * n - 1.0f) / n;
        const float fb = (n - 1.0f) / n;
        const int rb = wr + (lane >> 2);
        const int cb = wc + 2 * (lane & 3);
        if (n == 1) {
            #pragma unroll
            for (int mt = 0; mt < 2; mt++)
                #pragma unroll
                for (int nt = 0; nt < 4; nt++)
                    #pragma unroll
                    for (int f = 0; f < 4; f++) p1[mt][nt][f] = acc[mt][nt][f];
        } else if (n < DEG) {
            #pragma unroll
            for (int mt = 0; mt < 2; mt++)
                #pragma unroll
                for (int nt = 0; nt < 4; nt++)
                    #pragma unroll
                    for (int h = 0; h < 2; h++) {
                        const int r = rb + mt * 16 + h * 8;
                        const int c = cb + nt * 8;
                        float2 q2 = *(float2*)&prev2[r * P2_PITCH + c];
                        float g0 = acc[mt][nt][2 * h], g1 = acc[mt][nt][2 * h + 1];
                        float q10 = p1[mt][nt][2 * h], q11 = p1[mt][nt][2 * h + 1];
                        float c0 = fa * g0 * q10 - fb * q2.x;
                        float c1 = fa * g1 * q11 - fb * q2.y;
                        *(float2*)&prev2[r * P2_PITCH + c] = make_float2(q10, q11);
                        p1[mt][nt][2 * h] = c0;
                        p1[mt][nt][2 * h + 1] = c1;
                    }
        } else {
            // n == 8: cur -> out8 split bf16 hi/lo, direct to gmem
            #pragma unroll
            for (int mt = 0; mt < 2; mt++)
                #pragma unroll
                for (int nt = 0; nt < 4; nt++)
                    #pragma unroll
                    for (int h = 0; h < 2; h++) {
                        const int r = rb + mt * 16 + h * 8;
                        const int c = cb + nt * 8;
                        float2 q2 = *(float2*)&prev2[r * P2_PITCH + c];
                        float g0 = acc[mt][nt][2 * h], g1 = acc[mt][nt][2 * h + 1];
                        float c0 = fa * g0 * p1[mt][nt][2 * h]     - fb * q2.x;
                        float c1 = fa * g1 * p1[mt][nt][2 * h + 1] - fb * q2.y;
                        uint16_t h0 = f2bf_bits(c0), h1 = f2bf_bits(c1);
                        uint16_t l0 = f2bf_bits(c0 - bf2f(h0));
                        uint16_t l1 = f2bf_bits(c1 - bf2f(h1));
                        size_t idx = (size_t)(row0 + r) * KK + k0 + c;
                        *(uint32_t*)&g_o8_hi[idx] = (uint32_t)h0 | ((uint32_t)h1 << 16);
                        *(uint32_t*)&g_o8_lo[idx] = (uint32_t)l0 | ((uint32_t)l1 << 16);
                    }
        }
    }
}

// ---------------------------------------------------------------------------
// C kernel: out[N,512] = out8[N,256] @ Cw^T + Cb
// ---------------------------------------------------------------------------
#define C_SMEM (2 * ST_BYTES)

__global__ void __launch_bounds__(NTHR, 1)
cgemm_mma_kernel(const float* __restrict__ Cb, float* __restrict__ out) {
    extern __shared__ char smem[];
    const uint32_t sbase = smem_u32(smem);

    const int tid  = threadIdx.x;
    const int lane = tid & 31;
    const int wid  = tid >> 5;
    const int wr   = (wid & 3) * 32;
    const int wc   = (wid >> 2) * 32;
    const int o0   = blockIdx.x * 128;
    const int row0 = blockIdx.y * 128;

    float acc[2][4][4];
    #pragma unroll
    for (int mt = 0; mt < 2; mt++)
        #pragma unroll
        for (int nt = 0; nt < 4; nt++)
            #pragma unroll
            for (int f = 0; f < 4; f++) acc[mt][nt][f] = 0.0f;

    auto prefetch = [&](int stage, int j1) {
        const uint32_t st = sbase + stage * ST_BYTES;
        const int d0 = j1 * 64;
        load_tile<128, NTHR>(st + ST_AH, g_o8_hi + (size_t)row0 * KK + d0, KK, tid);
        load_tile<128, NTHR>(st + ST_AL, g_o8_lo + (size_t)row0 * KK + d0, KK, tid);
        load_tile<128, NTHR>(st + ST_BH, g_Cw_hi + (size_t)o0 * KK + d0, KK, tid);
        load_tile<128, NTHR>(st + ST_BL, g_Cw_lo + (size_t)o0 * KK + d0, KK, tid);
        cp_commit();
    };

    prefetch(0, 0);
    for (int j = 0; j < 4; j++) {
        if (j + 1 < 4) { prefetch((j + 1) & 1, j + 1); cp_wait<1>(); }
        else           { cp_wait<0>(); }
        __syncthreads();
        compute_chunk(sbase + (j & 1) * ST_BYTES, acc, wr, wc, lane);
        __syncthreads();
    }

    const int rb = wr + (lane >> 2);
    const int cb = wc + 2 * (lane & 3);
    #pragma unroll
    for (int nt = 0; nt < 4; nt++) {
        const int c = o0 + cb + nt * 8;
        float2 bias = *(const float2*)&Cb[c];
        #pragma unroll
        for (int mt = 0; mt < 2; mt++)
            #pragma unroll
            for (int h = 0; h < 2; h++) {
                const int r = row0 + rb + mt * 16 + h * 8;
                float2 v = make_float2(acc[mt][nt][2 * h] + bias.x,
                                       acc[mt][nt][2 * h + 1] + bias.y);
                *(float2*)&out[(size_t)r * OO + c] = v;
            }
    }
}

// ---------------------------------------------------------------------------
extern "C" void kernel_launch(void* const* d_in, const int* in_sizes, int n_in,
                              void* d_out, int out_size) {
    const float* z  = (const float*)d_in[0];
    const float* T0 = (const float*)d_in[1];
    const float* T  = (const float*)d_in[2];
    const float* Cw = (const float*)d_in[3];
    const float* Cb = (const float*)d_in[4];
    float* out = (float*)d_out;

    cudaFuncSetAttribute(poly_mma_kernel,  cudaFuncAttributeMaxDynamicSharedMemorySize, P_SMEM);
    cudaFuncSetAttribute(cgemm_mma_kernel, cudaFuncAttributeMaxDynamicSharedMemorySize, C_SMEM);

    split_kernel<<<1024, STHR>>>(z, T, Cw);

    dim3 g1(KK / 128, NN / 128);   // (2, 512)
    poly_mma_kernel<<<g1, NTHR, P_SMEM>>>(T0);

    dim3 g2(OO / 128, NN / 128);   // (4, 512)
    cgemm_mma_kernel<<<g2, NTHR, C_SMEM>>>(Cb, out);
}

// round 12
// speedup vs baseline: 1.0774x; 1.0774x over previous
#include <cuda_runtime.h>
#include <cuda_bf16.h>
#include <cstdint>
#include <cstddef>

#define NN 65536
#define DD 512
#define KK 256
#define OO 512
#define DEG 8
#define NTHR 256          // GEMM kernels
#define STHR 256          // split kernel

// ---------------- device-global scratch (allocation-free) ----------------
__device__ uint16_t g_z_hi[(size_t)NN * DD];          // 64 MB
__device__ uint16_t g_z_lo[(size_t)NN * DD];          // 64 MB
__device__ uint16_t g_T_hi[(size_t)DEG * KK * DD];    // 2 MB
__device__ uint16_t g_T_lo[(size_t)DEG * KK * DD];    // 2 MB
__device__ uint16_t g_Cw_hi[(size_t)OO * KK];         // 256 KB
__device__ uint16_t g_Cw_lo[(size_t)OO * KK];         // 256 KB
__device__ uint16_t g_o8_hi[(size_t)NN * KK];         // 32 MB
__device__ uint16_t g_o8_lo[(size_t)NN * KK];         // 32 MB

// ---------------- PTX helpers (sm_80-era only: valid on plain sm_103) ----
__device__ __forceinline__ uint32_t smem_u32(const void* p) {
    uint32_t a;
    asm("{ .reg .u64 t; cvta.to.shared.u64 t, %1; cvt.u32.u64 %0, t; }" : "=r"(a) : "l"(p));
    return a;
}
__device__ __forceinline__ void cp16(uint32_t dst, const void* src) {
    asm volatile("cp.async.cg.shared.global [%0], [%1], 16;" :: "r"(dst), "l"(src));
}
__device__ __forceinline__ void cp_commit() {
    asm volatile("cp.async.commit_group;" ::: "memory");
}
template <int N>
__device__ __forceinline__ void cp_wait() {
    asm volatile("cp.async.wait_group %0;" :: "n"(N) : "memory");
}
__device__ __forceinline__ void ldsm4(uint32_t* r, uint32_t addr) {
    asm volatile("ldmatrix.sync.aligned.m8n8.x4.shared.b16 {%0,%1,%2,%3}, [%4];"
                 : "=r"(r[0]), "=r"(r[1]), "=r"(r[2]), "=r"(r[3]) : "r"(addr));
}
__device__ __forceinline__ void mma_bf16(float* c, const uint32_t* a, uint32_t b0, uint32_t b1) {
    asm volatile(
        "mma.sync.aligned.m16n8k16.row.col.f32.bf16.bf16.f32 "
        "{%0,%1,%2,%3}, {%4,%5,%6,%7}, {%8,%9}, {%0,%1,%2,%3};"
        : "+f"(c[0]), "+f"(c[1]), "+f"(c[2]), "+f"(c[3])
        : "r"(a[0]), "r"(a[1]), "r"(a[2]), "r"(a[3]), "r"(b0), "r"(b1));
}
__device__ __forceinline__ uint32_t swz(uint32_t off) { return off ^ ((off >> 3) & 0x70); }

__device__ __forceinline__ uint16_t f2bf_bits(float x) {
    return __bfloat16_as_ushort(__float2bfloat16(x));
}
__device__ __forceinline__ float bf2f(uint16_t b) {
    return __bfloat162float(__ushort_as_bfloat16(b));
}

// load [ROWS x 64] bf16 tile -> SW128-swizzled smem (128B rows)
template <int ROWS, int THREADS>
__device__ __forceinline__ void load_tile(uint32_t smem_base, const uint16_t* src,
                                          size_t row_stride, int tid) {
    #pragma unroll 4
    for (int s = tid; s < ROWS * 8; s += THREADS) {
        int row = s >> 3, seg = s & 7;
        uint32_t off = (uint32_t)row * 128 + seg * 16;
        cp16(smem_base + swz(off), src + (size_t)row * row_stride + seg * 8);
    }
}

// ---------------------------------------------------------------------------
// split kernel: fp32 -> (hi, lo) bf16 pairs for z, T, Cw
// ---------------------------------------------------------------------------
__global__ void split_kernel(const float* __restrict__ z, const float* __restrict__ T,
                             const float* __restrict__ Cw) {
    const size_t gth = (size_t)blockIdx.x * blockDim.x + threadIdx.x;
    const size_t nth = (size_t)gridDim.x * blockDim.x;

    auto do_range = [&](const float* src, uint16_t* hi, uint16_t* lo, size_t n4) {
        for (size_t i = gth; i < n4; i += nth) {
            float4 v = ((const float4*)src)[i];
            uint16_t h0 = f2bf_bits(v.x), h1 = f2bf_bits(v.y);
            uint16_t h2 = f2bf_bits(v.z), h3 = f2bf_bits(v.w);
            uint16_t l0 = f2bf_bits(v.x - bf2f(h0));
            uint16_t l1 = f2bf_bits(v.y - bf2f(h1));
            uint16_t l2 = f2bf_bits(v.z - bf2f(h2));
            uint16_t l3 = f2bf_bits(v.w - bf2f(h3));
            ((uint2*)hi)[i] = make_uint2((uint32_t)h0 | ((uint32_t)h1 << 16),
                                         (uint32_t)h2 | ((uint32_t)h3 << 16));
            ((uint2*)lo)[i] = make_uint2((uint32_t)l0 | ((uint32_t)l1 << 16),
                                         (uint32_t)l2 | ((uint32_t)l3 << 16));
        }
    };
    do_range(z,  g_z_hi,  g_z_lo,  (size_t)NN * DD / 4);
    do_range(T,  g_T_hi,  g_T_lo,  (size_t)DEG * KK * DD / 4);
    do_range(Cw, g_Cw_hi, g_Cw_lo, (size_t)OO * KK / 4);
}

// ---------------------------------------------------------------------------
// Shared MMA-core: one chunk = [128 x 64] A x [128 x 64] B^T -> accumulate.
// Stage layout (64 KB): A_HI 0, A_LO 16K, B_HI 32K, B_LO 48K. 3 stages.
// 8 warps: wr = (wid&3)*32, wc = (wid>>2)*64 -> warp tile 32x64.
// acc[2][8][4]: m-tile(16), n-tile(8), frag. B frags loaded per-ng to cap regs.
// ---------------------------------------------------------------------------
#define ST_AH 0
#define ST_AL 16384
#define ST_BH 32768
#define ST_BL 49152
#define ST_BYTES 65536
#define NSTAGE 3

__device__ __forceinline__ void compute_chunk(uint32_t st, float acc[2][8][4],
                                              int wr, int wc, int lane) {
    const int l15 = lane & 15;
    const int lk  = (lane >> 4) << 4;      // 0 or 16 bytes
    #pragma unroll
    for (int ks = 0; ks < 4; ks++) {
        const uint32_t kb = ks * 32 + lk;
        uint32_t ah[2][4], al[2][4];
        #pragma unroll
        for (int mt = 0; mt < 2; mt++)
            ldsm4(ah[mt], st + ST_AH + swz((uint32_t)(wr + mt * 16 + l15) * 128 + kb));
        #pragma unroll
        for (int mt = 0; mt < 2; mt++)
            ldsm4(al[mt], st + ST_AL + swz((uint32_t)(wr + mt * 16 + l15) * 128 + kb));
        #pragma unroll
        for (int ng = 0; ng < 4; ng++) {
            uint32_t bh[4], bl[4];
            ldsm4(bh, st + ST_BH + swz((uint32_t)(wc + ng * 16 + l15) * 128 + kb));
            #pragma unroll
            for (int mt = 0; mt < 2; mt++) {      // hi*hi
                mma_bf16(acc[mt][2 * ng],     ah[mt], bh[0], bh[2]);
                mma_bf16(acc[mt][2 * ng + 1], ah[mt], bh[1], bh[3]);
            }
            #pragma unroll
            for (int mt = 0; mt < 2; mt++) {      // lo*hi
                mma_bf16(acc[mt][2 * ng],     al[mt], bh[0], bh[2]);
                mma_bf16(acc[mt][2 * ng + 1], al[mt], bh[1], bh[3]);
            }
            ldsm4(bl, st + ST_BL + swz((uint32_t)(wc + ng * 16 + l15) * 128 + kb));
            #pragma unroll
            for (int mt = 0; mt < 2; mt++) {      // hi*lo
                mma_bf16(acc[mt][2 * ng],     ah[mt], bl[0], bl[2]);
                mma_bf16(acc[mt][2 * ng + 1], ah[mt], bl[1], bl[3]);
            }
        }
    }
}

// ---------------------------------------------------------------------------
// poly kernel: fused Legendre recurrence, all state (G, p1, p2) in registers.
// CTA: 128 rows x 128 K-cols, 256 threads, 3-stage cp.async, 1 sync/chunk.
// ---------------------------------------------------------------------------
#define P_SMEM  (NSTAGE * ST_BYTES)                  // 196608

__global__ void __launch_bounds__(NTHR, 1)
poly_mma_kernel(const float* __restrict__ T0) {
    extern __shared__ char smem[];
    const uint32_t sbase = smem_u32(smem);

    const int tid  = threadIdx.x;
    const int lane = tid & 31;
    const int wid  = tid >> 5;
    const int wr   = (wid & 3) * 32;   // warp row base
    const int wc   = (wid >> 2) * 64;  // warp col base
    const int k0   = blockIdx.x * 128;
    const int row0 = blockIdx.y * 128;
    const int rb   = wr + (lane >> 2);
    const int cb   = wc + 2 * (lane & 3);

    float acc[2][8][4], p1[2][8][4], p2[2][8][4];

    // p2 init = T0[k] broadcast over rows (degree 0); layout matches fragments
    #pragma unroll
    for (int nt = 0; nt < 8; nt++) {
        float t0 = __ldg(&T0[k0 + cb + nt * 8]);
        float t1 = __ldg(&T0[k0 + cb + nt * 8 + 1]);
        #pragma unroll
        for (int mt = 0; mt < 2; mt++) {
            p2[mt][nt][0] = t0; p2[mt][nt][1] = t1;
            p2[mt][nt][2] = t0; p2[mt][nt][3] = t1;
        }
    }

    // gi = global chunk index: degree = gi>>3, D-chunk = gi&7
    auto prefetch = [&](int stage, int gi) {
        const uint32_t st = sbase + stage * ST_BYTES;
        const int nd = gi >> 3;
        const int d0 = (gi & 7) * 64;
        const uint16_t* Th = g_T_hi + (size_t)nd * KK * DD + (size_t)k0 * DD + d0;
        const uint16_t* Tl = g_T_lo + (size_t)nd * KK * DD + (size_t)k0 * DD + d0;
        load_tile<128, NTHR>(st + ST_AH, g_z_hi + (size_t)row0 * DD + d0, DD, tid);
        load_tile<128, NTHR>(st + ST_AL, g_z_lo + (size_t)row0 * DD + d0, DD, tid);
        load_tile<128, NTHR>(st + ST_BH, Th, DD, tid);
        load_tile<128, NTHR>(st + ST_BL, Tl, DD, tid);
        cp_commit();
    };

    prefetch(0, 0);
    prefetch(1, 1);
    int it = 0;

    for (int n = 1; n <= DEG; n++) {
        #pragma unroll
        for (int mt = 0; mt < 2; mt++)
            #pragma unroll
            for (int nt = 0; nt < 8; nt++)
                #pragma unroll
                for (int f = 0; f < 4; f++) acc[mt][nt][f] = 0.0f;

        for (int j = 0; j < 8; j++) {
            if (it < 8 * DEG - 2) cp_wait<1>();
            else                  cp_wait<0>();
            __syncthreads();
            // safe: all warps have finished reading stage (it-1)%3 == (it+2)%3
            if (it + 2 < 8 * DEG) prefetch((it + 2) % NSTAGE, it + 2);
            compute_chunk(sbase + (it % NSTAGE) * ST_BYTES, acc, wr, wc, lane);
            it++;
        }

        // ---- recurrence epilogue (pure registers, no smem, no sync) ----
        const float fa = (2.0f * n - 1.0f) / n;
        const float fb = (n - 1.0f) / n;
        if (n == 1) {
            #pragma unroll
            for (int mt = 0; mt < 2; mt++)
                #pragma unroll
                for (int nt = 0; nt < 8; nt++)
                    #pragma unroll
                    for (int f = 0; f < 4; f++) p1[mt][nt][f] = acc[mt][nt][f];
        } else if (n < DEG) {
            #pragma unroll
            for (int mt = 0; mt < 2; mt++)
                #pragma unroll
                for (int nt = 0; nt < 8; nt++)
                    #pragma unroll
                    for (int f = 0; f < 4; f++) {
                        float cur = fa * acc[mt][nt][f] * p1[mt][nt][f] - fb * p2[mt][nt][f];
                        p2[mt][nt][f] = p1[mt][nt][f];
                        p1[mt][nt][f] = cur;
                    }
        } else {
            // n == 8: cur -> out8 split bf16 hi/lo, direct to gmem
            #pragma unroll
            for (int mt = 0; mt < 2; mt++)
                #pragma unroll
                for (int nt = 0; nt < 8; nt++)
                    #pragma unroll
                    for (int h = 0; h < 2; h++) {
                        const int r = rb + mt * 16 + h * 8;
                        const int c = cb + nt * 8;
                        float c0 = fa * acc[mt][nt][2 * h]     * p1[mt][nt][2 * h]
                                 - fb * p2[mt][nt][2 * h];
                        float c1 = fa * acc[mt][nt][2 * h + 1] * p1[mt][nt][2 * h + 1]
                                 - fb * p2[mt][nt][2 * h + 1];
                        uint16_t h0 = f2bf_bits(c0), h1 = f2bf_bits(c1);
                        uint16_t l0 = f2bf_bits(c0 - bf2f(h0));
                        uint16_t l1 = f2bf_bits(c1 - bf2f(h1));
                        size_t idx = (size_t)(row0 + r) * KK + k0 + c;
                        *(uint32_t*)&g_o8_hi[idx] = (uint32_t)h0 | ((uint32_t)h1 << 16);
                        *(uint32_t*)&g_o8_lo[idx] = (uint32_t)l0 | ((uint32_t)l1 << 16);
                    }
        }
    }
}

// ---------------------------------------------------------------------------
// C kernel: out[N,512] = out8[N,256] @ Cw^T + Cb  (3-stage, 1 sync/chunk)
// ---------------------------------------------------------------------------
#define C_SMEM (NSTAGE * ST_BYTES)

__global__ void __launch_bounds__(NTHR, 1)
cgemm_mma_kernel(const float* __restrict__ Cb, float* __restrict__ out) {
    extern __shared__ char smem[];
    const uint32_t sbase = smem_u32(smem);

    const int tid  = threadIdx.x;
    const int lane = tid & 31;
    const int wid  = tid >> 5;
    const int wr   = (wid & 3) * 32;
    const int wc   = (wid >> 2) * 64;
    const int o0   = blockIdx.x * 128;
    const int row0 = blockIdx.y * 128;

    float acc[2][8][4];
    #pragma unroll
    for (int mt = 0; mt < 2; mt++)
        #pragma unroll
        for (int nt = 0; nt < 8; nt++)
            #pragma unroll
            for (int f = 0; f < 4; f++) acc[mt][nt][f] = 0.0f;

    auto prefetch = [&](int stage, int j1) {
        const uint32_t st = sbase + stage * ST_BYTES;
        const int d0 = j1 * 64;
        load_tile<128, NTHR>(st + ST_AH, g_o8_hi + (size_t)row0 * KK + d0, KK, tid);
        load_tile<128, NTHR>(st + ST_AL, g_o8_lo + (size_t)row0 * KK + d0, KK, tid);
        load_tile<128, NTHR>(st + ST_BH, g_Cw_hi + (size_t)o0 * KK + d0, KK, tid);
        load_tile<128, NTHR>(st + ST_BL, g_Cw_lo + (size_t)o0 * KK + d0, KK, tid);
        cp_commit();
    };

    prefetch(0, 0);
    prefetch(1, 1);
    for (int j = 0; j < 4; j++) {
        if (j < 2) cp_wait<1>();
        else       cp_wait<0>();
        __syncthreads();
        if (j + 2 < 4) prefetch((j + 2) % NSTAGE, j + 2);
        compute_chunk(sbase + (j % NSTAGE) * ST_BYTES, acc, wr, wc, lane);
    }

    const int rb = wr + (lane >> 2);
    const int cb = wc + 2 * (lane & 3);
    #pragma unroll
    for (int nt = 0; nt < 8; nt++) {
        const int c = o0 + cb + nt * 8;
        float2 bias = *(const float2*)&Cb[c];
        #pragma unroll
        for (int mt = 0; mt < 2; mt++)
            #pragma unroll
            for (int h = 0; h < 2; h++) {
                const int r = row0 + rb + mt * 16 + h * 8;
                float2 v = make_float2(acc[mt][nt][2 * h] + bias.x,
                                       acc[mt][nt][2 * h + 1] + bias.y);
                *(float2*)&out[(size_t)r * OO + c] = v;
            }
    }
}

// ---------------------------------------------------------------------------
extern "C" void kernel_launch(void* const* d_in, const int* in_sizes, int n_in,
                              void* d_out, int out_size) {
    const float* z  = (const float*)d_in[0];
    const float* T0 = (const float*)d_in[1];
    const float* T  = (const float*)d_in[2];
    const float* Cw = (const float*)d_in[3];
    const float* Cb = (const float*)d_in[4];
    float* out = (float*)d_out;

    cudaFuncSetAttribute(poly_mma_kernel,  cudaFuncAttributeMaxDynamicSharedMemorySize, P_SMEM);
    cudaFuncSetAttribute(cgemm_mma_kernel, cudaFuncAttributeMaxDynamicSharedMemorySize, C_SMEM);

    split_kernel<<<1024, STHR>>>(z, T, Cw);

    dim3 g1(KK / 128, NN / 128);   // (2, 512)
    poly_mma_kernel<<<g1, NTHR, P_SMEM>>>(T0);

    dim3 g2(OO / 128, NN / 128);   // (4, 512)
    cgemm_mma_kernel<<<g2, NTHR, C_SMEM>>>(Cb, out);
}

// round 14
// speedup vs baseline: 1.1567x; 1.0737x over previous
#include <cuda_runtime.h>
#include <cuda.h>
#include <cuda_bf16.h>
#include <dlfcn.h>
#include <cstdint>
#include <cstddef>

#define NN 65536
#define DD 512
#define KK 256
#define OO 512
#define DEG 8
#define NTHR 256          // GEMM kernels
#define STHR 256          // split kernel

// ---------------- device-global scratch (allocation-free) ----------------
__device__ uint16_t g_z_hi[(size_t)NN * DD];          // 64 MB
__device__ uint16_t g_z_lo[(size_t)NN * DD];          // 64 MB
__device__ uint16_t g_T_hi[(size_t)DEG * KK * DD];    // 2 MB
__device__ uint16_t g_T_lo[(size_t)DEG * KK * DD];    // 2 MB
__device__ uint16_t g_Cw_hi[(size_t)OO * KK];         // 256 KB
__device__ uint16_t g_Cw_lo[(size_t)OO * KK];         // 256 KB
__device__ uint16_t g_o8_hi[(size_t)NN * KK];         // 32 MB
__device__ uint16_t g_o8_lo[(size_t)NN * KK];         // 32 MB

// ---------------- PTX helpers (base sm_90-era: valid on plain sm_103) ----
__device__ __forceinline__ uint32_t smem_u32(const void* p) {
    uint32_t a;
    asm("{ .reg .u64 t; cvta.to.shared.u64 t, %1; cvt.u32.u64 %0, t; }" : "=r"(a) : "l"(p));
    return a;
}
__device__ __forceinline__ void mbar_init(uint32_t mbar, uint32_t cnt) {
    asm volatile("mbarrier.init.shared.b64 [%0], %1;" :: "r"(mbar), "r"(cnt) : "memory");
}
__device__ __forceinline__ void mbar_expect_tx(uint32_t mbar, uint32_t tx) {
    asm volatile("mbarrier.arrive.expect_tx.shared.b64 _, [%0], %1;"
                 :: "r"(mbar), "r"(tx) : "memory");
}
__device__ __forceinline__ void mbar_wait(uint32_t mbar, uint32_t parity) {
    asm volatile(
        "{\n\t.reg .pred P;\n"
        "W%=:\n\t"
        "mbarrier.try_wait.parity.acquire.cta.shared::cta.b64 P, [%0], %1, 0x989680;\n\t"
        "@!P bra W%=;\n\t}"
        :: "r"(mbar), "r"(parity) : "memory");
}
__device__ __forceinline__ void tma2d(uint32_t dst, const void* map, int cx, int cy,
                                      uint32_t mbar) {
    asm volatile(
        "cp.async.bulk.tensor.2d.shared::cluster.global.tile.mbarrier::complete_tx::bytes "
        "[%0], [%1, {%2, %3}], [%4];"
        :: "r"(dst), "l"(map), "r"(cx), "r"(cy), "r"(mbar) : "memory");
}
#define FENCE_PROXY() asm volatile("fence.proxy.async.shared::cta;" ::: "memory")

__device__ __forceinline__ void ldsm4(uint32_t* r, uint32_t addr) {
    asm volatile("ldmatrix.sync.aligned.m8n8.x4.shared.b16 {%0,%1,%2,%3}, [%4];"
                 : "=r"(r[0]), "=r"(r[1]), "=r"(r[2]), "=r"(r[3]) : "r"(addr));
}
__device__ __forceinline__ void mma_bf16(float* c, const uint32_t* a, uint32_t b0, uint32_t b1) {
    asm volatile(
        "mma.sync.aligned.m16n8k16.row.col.f32.bf16.bf16.f32 "
        "{%0,%1,%2,%3}, {%4,%5,%6,%7}, {%8,%9}, {%0,%1,%2,%3};"
        : "+f"(c[0]), "+f"(c[1]), "+f"(c[2]), "+f"(c[3])
        : "r"(a[0]), "r"(a[1]), "r"(a[2]), "r"(a[3]), "r"(b0), "r"(b1));
}
__device__ __forceinline__ uint32_t swz(uint32_t off) { return off ^ ((off >> 3) & 0x70); }

__device__ __forceinline__ uint16_t f2bf_bits(float x) {
    return __bfloat16_as_ushort(__float2bfloat16(x));
}
__device__ __forceinline__ float bf2f(uint16_t b) {
    return __bfloat162float(__ushort_as_bfloat16(b));
}

// ---------------------------------------------------------------------------
// split kernel: fp32 -> (hi, lo) bf16 pairs for z, T, Cw
// ---------------------------------------------------------------------------
__global__ void split_kernel(const float* __restrict__ z, const float* __restrict__ T,
                             const float* __restrict__ Cw) {
    const size_t gth = (size_t)blockIdx.x * blockDim.x + threadIdx.x;
    const size_t nth = (size_t)gridDim.x * blockDim.x;

    auto do_range = [&](const float* src, uint16_t* hi, uint16_t* lo, size_t n4) {
        for (size_t i = gth; i < n4; i += nth) {
            float4 v = ((const float4*)src)[i];
            uint16_t h0 = f2bf_bits(v.x), h1 = f2bf_bits(v.y);
            uint16_t h2 = f2bf_bits(v.z), h3 = f2bf_bits(v.w);
            uint16_t l0 = f2bf_bits(v.x - bf2f(h0));
            uint16_t l1 = f2bf_bits(v.y - bf2f(h1));
            uint16_t l2 = f2bf_bits(v.z - bf2f(h2));
            uint16_t l3 = f2bf_bits(v.w - bf2f(h3));
            ((uint2*)hi)[i] = make_uint2((uint32_t)h0 | ((uint32_t)h1 << 16),
                                         (uint32_t)h2 | ((uint32_t)h3 << 16));
            ((uint2*)lo)[i] = make_uint2((uint32_t)l0 | ((uint32_t)l1 << 16),
                                         (uint32_t)l2 | ((uint32_t)l3 << 16));
        }
    };
    do_range(z,  g_z_hi,  g_z_lo,  (size_t)NN * DD / 4);
    do_range(T,  g_T_hi,  g_T_lo,  (size_t)DEG * KK * DD / 4);
    do_range(Cw, g_Cw_hi, g_Cw_lo, (size_t)OO * KK / 4);
}

// ---------------------------------------------------------------------------
// Shared MMA-core: one chunk = [128 x 64] A x [128 x 64] B^T -> accumulate.
// Stage layout (64 KB): A_HI 0, A_LO 16K, B_HI 32K, B_LO 48K. 3 stages.
// 8 warps: wr = (wid&3)*32, wc = (wid>>2)*64 -> warp tile 32x64.
// ---------------------------------------------------------------------------
#define ST_AH 0
#define ST_AL 16384
#define ST_BH 32768
#define ST_BL 49152
#define ST_BYTES 65536
#define NSTAGE 3
#define MBAR_OFF (NSTAGE * ST_BYTES)                 // 196608
#define GSMEM (MBAR_OFF + 64)                        // stages + mbarriers

__device__ __forceinline__ void compute_chunk(uint32_t st, float acc[2][8][4],
                                              int wr, int wc, int lane) {
    const int l15 = lane & 15;
    const int lk  = (lane >> 4) << 4;      // 0 or 16 bytes
    #pragma unroll
    for (int ks = 0; ks < 4; ks++) {
        const uint32_t kb = ks * 32 + lk;
        uint32_t ah[2][4], al[2][4];
        #pragma unroll
        for (int mt = 0; mt < 2; mt++)
            ldsm4(ah[mt], st + ST_AH + swz((uint32_t)(wr + mt * 16 + l15) * 128 + kb));
        #pragma unroll
        for (int mt = 0; mt < 2; mt++)
            ldsm4(al[mt], st + ST_AL + swz((uint32_t)(wr + mt * 16 + l15) * 128 + kb));
        #pragma unroll
        for (int ng = 0; ng < 4; ng++) {
            uint32_t bh[4], bl[4];
            ldsm4(bh, st + ST_BH + swz((uint32_t)(wc + ng * 16 + l15) * 128 + kb));
            #pragma unroll
            for (int mt = 0; mt < 2; mt++) {      // hi*hi
                mma_bf16(acc[mt][2 * ng],     ah[mt], bh[0], bh[2]);
                mma_bf16(acc[mt][2 * ng + 1], ah[mt], bh[1], bh[3]);
            }
            #pragma unroll
            for (int mt = 0; mt < 2; mt++) {      // lo*hi
                mma_bf16(acc[mt][2 * ng],     al[mt], bh[0], bh[2]);
                mma_bf16(acc[mt][2 * ng + 1], al[mt], bh[1], bh[3]);
            }
            ldsm4(bl, st + ST_BL + swz((uint32_t)(wc + ng * 16 + l15) * 128 + kb));
            #pragma unroll
            for (int mt = 0; mt < 2; mt++) {      // hi*lo
                mma_bf16(acc[mt][2 * ng],     ah[mt], bl[0], bl[2]);
                mma_bf16(acc[mt][2 * ng + 1], ah[mt], bl[1], bl[3]);
            }
        }
    }
}

// ---------------------------------------------------------------------------
// poly kernel: fused Legendre recurrence, all state (G, p1, p2) in registers.
// TMA staging, 3 stages, 1 syncthreads per chunk.
// ---------------------------------------------------------------------------
__global__ void __launch_bounds__(NTHR, 1)
poly_mma_kernel(const float* __restrict__ T0,
                const __grid_constant__ CUtensorMap mZH,
                const __grid_constant__ CUtensorMap mZL,
                const __grid_constant__ CUtensorMap mTH,
                const __grid_constant__ CUtensorMap mTL) {
    extern __shared__ char smem[];
    const uint32_t sbase = smem_u32(smem);

    const int tid  = threadIdx.x;
    const int lane = tid & 31;
    const int wid  = tid >> 5;
    const int wr   = (wid & 3) * 32;   // warp row base
    const int wc   = (wid >> 2) * 64;  // warp col base
    const int k0   = blockIdx.x * 128;
    const int row0 = blockIdx.y * 128;
    const int rb   = wr + (lane >> 2);
    const int cb   = wc + 2 * (lane & 3);

    if (tid == 0) {
        #pragma unroll
        for (int s = 0; s < NSTAGE; s++) mbar_init(sbase + MBAR_OFF + s * 8, 1);
        FENCE_PROXY();
    }
    __syncthreads();

    float acc[2][8][4], p1[2][8][4], p2[2][8][4];

    // p2 init = T0[k] broadcast over rows (degree 0); layout matches fragments
    #pragma unroll
    for (int nt = 0; nt < 8; nt++) {
        float t0 = __ldg(&T0[k0 + cb + nt * 8]);
        float t1 = __ldg(&T0[k0 + cb + nt * 8 + 1]);
        #pragma unroll
        for (int mt = 0; mt < 2; mt++) {
            p2[mt][nt][0] = t0; p2[mt][nt][1] = t1;
            p2[mt][nt][2] = t0; p2[mt][nt][3] = t1;
        }
    }

    // gi = global chunk index: degree = gi>>3, D-chunk = gi&7
    auto prefetch = [&](int stage, int gi) {
        if (tid == 0) {
            const uint32_t st = sbase + stage * ST_BYTES;
            const uint32_t mb = sbase + MBAR_OFF + stage * 8;
            const int nd = gi >> 3;
            const int d0 = (gi & 7) * 64;
            mbar_expect_tx(mb, 4 * 16384);
            tma2d(st + ST_AH, &mZH, d0, row0, mb);
            tma2d(st + ST_AL, &mZL, d0, row0, mb);
            tma2d(st + ST_BH, &mTH, d0, nd * KK + k0, mb);
            tma2d(st + ST_BL, &mTL, d0, nd * KK + k0, mb);
        }
    };

    prefetch(0, 0);
    prefetch(1, 1);
    int it = 0;

    for (int n = 1; n <= DEG; n++) {
        #pragma unroll
        for (int mt = 0; mt < 2; mt++)
            #pragma unroll
            for (int nt = 0; nt < 8; nt++)
                #pragma unroll
                for (int f = 0; f < 4; f++) acc[mt][nt][f] = 0.0f;

        for (int j = 0; j < 8; j++) {
            mbar_wait(sbase + MBAR_OFF + (it % NSTAGE) * 8, (it / NSTAGE) & 1);
            __syncthreads();
            // safe: all warps finished reading stage (it-1)%3 == (it+2)%3
            if (it + 2 < 8 * DEG) prefetch((it + 2) % NSTAGE, it + 2);
            compute_chunk(sbase + (it % NSTAGE) * ST_BYTES, acc, wr, wc, lane);
            it++;
        }

        // ---- recurrence epilogue (pure registers) ----
        const float fa = (2.0f * n - 1.0f) / n;
        const float fb = (n - 1.0f) / n;
        if (n == 1) {
            #pragma unroll
            for (int mt = 0; mt < 2; mt++)
                #pragma unroll
                for (int nt = 0; nt < 8; nt++)
                    #pragma unroll
                    for (int f = 0; f < 4; f++) p1[mt][nt][f] = acc[mt][nt][f];
        } else if (n < DEG) {
            #pragma unroll
            for (int mt = 0; mt < 2; mt++)
                #pragma unroll
                for (int nt = 0; nt < 8; nt++)
                    #pragma unroll
                    for (int f = 0; f < 4; f++) {
                        float cur = fa * acc[mt][nt][f] * p1[mt][nt][f] - fb * p2[mt][nt][f];
                        p2[mt][nt][f] = p1[mt][nt][f];
                        p1[mt][nt][f] = cur;
                    }
        } else {
            // n == 8: cur -> out8 split bf16 hi/lo, direct to gmem
            #pragma unroll
            for (int mt = 0; mt < 2; mt++)
                #pragma unroll
                for (int nt = 0; nt < 8; nt++)
                    #pragma unroll
                    for (int h = 0; h < 2; h++) {
                        const int r = rb + mt * 16 + h * 8;
                        const int c = cb + nt * 8;
                        float c0 = fa * acc[mt][nt][2 * h]     * p1[mt][nt][2 * h]
                                 - fb * p2[mt][nt][2 * h];
                        float c1 = fa * acc[mt][nt][2 * h + 1] * p1[mt][nt][2 * h + 1]
                                 - fb * p2[mt][nt][2 * h + 1];
                        uint16_t h0 = f2bf_bits(c0), h1 = f2bf_bits(c1);
                        uint16_t l0 = f2bf_bits(c0 - bf2f(h0));
                        uint16_t l1 = f2bf_bits(c1 - bf2f(h1));
                        size_t idx = (size_t)(row0 + r) * KK + k0 + c;
                        *(uint32_t*)&g_o8_hi[idx] = (uint32_t)h0 | ((uint32_t)h1 << 16);
                        *(uint32_t*)&g_o8_lo[idx] = (uint32_t)l0 | ((uint32_t)l1 << 16);
                    }
        }
    }
}

// ---------------------------------------------------------------------------
// C kernel: out[N,512] = out8[N,256] @ Cw^T + Cb  (TMA, 3-stage)
// ---------------------------------------------------------------------------
__global__ void __launch_bounds__(NTHR, 1)
cgemm_mma_kernel(const float* __restrict__ Cb, float* __restrict__ out,
                 const __grid_constant__ CUtensorMap mOH,
                 const __grid_constant__ CUtensorMap mOL,
                 const __grid_constant__ CUtensorMap mCH,
                 const __grid_constant__ CUtensorMap mCL) {
    extern __shared__ char smem[];
    const uint32_t sbase = smem_u32(smem);

    const int tid  = threadIdx.x;
    const int lane = tid & 31;
    const int wid  = tid >> 5;
    const int wr   = (wid & 3) * 32;
    const int wc   = (wid >> 2) * 64;
    const int o0   = blockIdx.x * 128;
    const int row0 = blockIdx.y * 128;

    if (tid == 0) {
        #pragma unroll
        for (int s = 0; s < NSTAGE; s++) mbar_init(sbase + MBAR_OFF + s * 8, 1);
        FENCE_PROXY();
    }
    __syncthreads();

    float acc[2][8][4];
    #pragma unroll
    for (int mt = 0; mt < 2; mt++)
        #pragma unroll
        for (int nt = 0; nt < 8; nt++)
            #pragma unroll
            for (int f = 0; f < 4; f++) acc[mt][nt][f] = 0.0f;

    auto prefetch = [&](int stage, int j1) {
        if (tid == 0) {
            const uint32_t st = sbase + stage * ST_BYTES;
            const uint32_t mb = sbase + MBAR_OFF + stage * 8;
            const int d0 = j1 * 64;
            mbar_expect_tx(mb, 4 * 16384);
            tma2d(st + ST_AH, &mOH, d0, row0, mb);
            tma2d(st + ST_AL, &mOL, d0, row0, mb);
            tma2d(st + ST_BH, &mCH, d0, o0, mb);
            tma2d(st + ST_BL, &mCL, d0, o0, mb);
        }
    };

    prefetch(0, 0);
    prefetch(1, 1);
    for (int j = 0; j < 4; j++) {
        mbar_wait(sbase + MBAR_OFF + (j % NSTAGE) * 8, (j / NSTAGE) & 1);
        __syncthreads();
        if (j + 2 < 4) prefetch((j + 2) % NSTAGE, j + 2);
        compute_chunk(sbase + (j % NSTAGE) * ST_BYTES, acc, wr, wc, lane);
    }

    const int rb = wr + (lane >> 2);
    const int cb = wc + 2 * (lane & 3);
    #pragma unroll
    for (int nt = 0; nt < 8; nt++) {
        const int c = o0 + cb + nt * 8;
        float2 bias = *(const float2*)&Cb[c];
        #pragma unroll
        for (int mt = 0; mt < 2; mt++)
            #pragma unroll
            for (int h = 0; h < 2; h++) {
                const int r = row0 + rb + mt * 16 + h * 8;
                float2 v = make_float2(acc[mt][nt][2 * h] + bias.x,
                                       acc[mt][nt][2 * h + 1] + bias.y);
                *(float2*)&out[(size_t)r * OO + c] = v;
            }
    }
}

// ---------------------------------------------------------------------------
// Host: build tensormaps (driver API via dlopen — no link-line change),
// launch the three kernels. No statics, fully deterministic per call.
// ---------------------------------------------------------------------------
typedef decltype(&cuTensorMapEncodeTiled) EncodeFn;

static void enc2d(EncodeFn fn, CUtensorMap* m, void* base,
                  uint64_t d0, uint64_t d1, uint64_t stride_bytes) {
    cuuint64_t gd[2] = {d0, d1};
    cuuint64_t gs[1] = {stride_bytes};
    cuuint32_t box[2] = {64, 128};
    cuuint32_t es[2] = {1, 1};
    fn(m, CU_TENSOR_MAP_DATA_TYPE_BFLOAT16, 2, base, gd, gs, box, es,
       CU_TENSOR_MAP_INTERLEAVE_NONE, CU_TENSOR_MAP_SWIZZLE_128B,
       CU_TENSOR_MAP_L2_PROMOTION_L2_128B, CU_TENSOR_MAP_FLOAT_OOB_FILL_NONE);
}

extern "C" void kernel_launch(void* const* d_in, const int* in_sizes, int n_in,
                              void* d_out, int out_size) {
    const float* z  = (const float*)d_in[0];
    const float* T0 = (const float*)d_in[1];
    const float* T  = (const float*)d_in[2];
    const float* Cw = (const float*)d_in[3];
    const float* Cb = (const float*)d_in[4];
    float* out = (float*)d_out;

    // resolve driver encode fn (libcuda is already loaded in-process)
    void* h = dlopen("libcuda.so.1", RTLD_NOW | RTLD_GLOBAL);
    EncodeFn fn = (EncodeFn)dlsym(h, "cuTensorMapEncodeTiled");

    void *p_zh, *p_zl, *p_th, *p_tl, *p_ch, *p_cl, *p_oh, *p_ol;
    cudaGetSymbolAddress(&p_zh, g_z_hi);
    cudaGetSymbolAddress(&p_zl, g_z_lo);
    cudaGetSymbolAddress(&p_th, g_T_hi);
    cudaGetSymbolAddress(&p_tl, g_T_lo);
    cudaGetSymbolAddress(&p_ch, g_Cw_hi);
    cudaGetSymbolAddress(&p_cl, g_Cw_lo);
    cudaGetSymbolAddress(&p_oh, g_o8_hi);
    cudaGetSymbolAddress(&p_ol, g_o8_lo);

    CUtensorMap mZH, mZL, mTH, mTL, mOH, mOL, mCH, mCL;
    enc2d(fn, &mZH, p_zh, DD, NN,       DD * 2);
    enc2d(fn, &mZL, p_zl, DD, NN,       DD * 2);
    enc2d(fn, &mTH, p_th, DD, DEG * KK, DD * 2);
    enc2d(fn, &mTL, p_tl, DD, DEG * KK, DD * 2);
    enc2d(fn, &mOH, p_oh, KK, NN,       KK * 2);
    enc2d(fn, &mOL, p_ol, KK, NN,       KK * 2);
    enc2d(fn, &mCH, p_ch, KK, OO,       KK * 2);
    enc2d(fn, &mCL, p_cl, KK, OO,       KK * 2);

    cudaFuncSetAttribute(poly_mma_kernel,  cudaFuncAttributeMaxDynamicSharedMemorySize, GSMEM);
    cudaFuncSetAttribute(cgemm_mma_kernel, cudaFuncAttributeMaxDynamicSharedMemorySize, GSMEM);

    split_kernel<<<1024, STHR>>>(z, T, Cw);

    dim3 g1(KK / 128, NN / 128);   // (2, 512)
    poly_mma_kernel<<<g1, NTHR, GSMEM>>>(T0, mZH, mZL, mTH, mTL);

    dim3 g2(OO / 128, NN / 128);   // (4, 512)
    cgemm_mma_kernel<<<g2, NTHR, GSMEM>>>(Cb, out, mOH, mOL, mCH, mCL);
}

// round 15
// speedup vs baseline: 1.1808x; 1.0208x over previous
#include <cuda_runtime.h>
#include <cuda.h>
#include <cuda_bf16.h>
#include <dlfcn.h>
#include <cstdint>
#include <cstddef>

#define NN 65536
#define DD 512
#define KK 256
#define OO 512
#define DEG 8
#define NTHR 256          // GEMM kernels
#define STHR 256          // split kernel

// ---------------- device-global scratch (allocation-free) ----------------
__device__ uint16_t g_z_hi[(size_t)NN * DD];          // 64 MB
__device__ uint16_t g_z_lo[(size_t)NN * DD];          // 64 MB
__device__ uint16_t g_T_hi[(size_t)DEG * KK * DD];    // 2 MB
__device__ uint16_t g_T_lo[(size_t)DEG * KK * DD];    // 2 MB
__device__ uint16_t g_Cw_hi[(size_t)OO * KK];         // 256 KB
__device__ uint16_t g_Cw_lo[(size_t)OO * KK];         // 256 KB
__device__ uint16_t g_o8_hi[(size_t)NN * KK];         // 32 MB
__device__ uint16_t g_o8_lo[(size_t)NN * KK];         // 32 MB

// ---------------- PTX helpers (base sm_90-era: valid on plain sm_103) ----
__device__ __forceinline__ uint32_t smem_u32(const void* p) {
    uint32_t a;
    asm("{ .reg .u64 t; cvta.to.shared.u64 t, %1; cvt.u32.u64 %0, t; }" : "=r"(a) : "l"(p));
    return a;
}
__device__ __forceinline__ void mbar_init(uint32_t mbar, uint32_t cnt) {
    asm volatile("mbarrier.init.shared.b64 [%0], %1;" :: "r"(mbar), "r"(cnt) : "memory");
}
__device__ __forceinline__ void mbar_expect_tx(uint32_t mbar, uint32_t tx) {
    asm volatile("mbarrier.arrive.expect_tx.shared.b64 _, [%0], %1;"
                 :: "r"(mbar), "r"(tx) : "memory");
}
__device__ __forceinline__ void mbar_arrive(uint32_t mbar) {
    asm volatile("mbarrier.arrive.shared.b64 _, [%0];" :: "r"(mbar) : "memory");
}
__device__ __forceinline__ void mbar_wait(uint32_t mbar, uint32_t parity) {
    asm volatile(
        "{\n\t.reg .pred P;\n"
        "W%=:\n\t"
        "mbarrier.try_wait.parity.acquire.cta.shared::cta.b64 P, [%0], %1, 0x989680;\n\t"
        "@!P bra W%=;\n\t}"
        :: "r"(mbar), "r"(parity) : "memory");
}
__device__ __forceinline__ void tma2d(uint32_t dst, const void* map, int cx, int cy,
                                      uint32_t mbar) {
    asm volatile(
        "cp.async.bulk.tensor.2d.shared::cluster.global.tile.mbarrier::complete_tx::bytes "
        "[%0], [%1, {%2, %3}], [%4];"
        :: "r"(dst), "l"(map), "r"(cx), "r"(cy), "r"(mbar) : "memory");
}
#define FENCE_PROXY() asm volatile("fence.proxy.async.shared::cta;" ::: "memory")

__device__ __forceinline__ void ldsm4(uint32_t* r, uint32_t addr) {
    asm volatile("ldmatrix.sync.aligned.m8n8.x4.shared.b16 {%0,%1,%2,%3}, [%4];"
                 : "=r"(r[0]), "=r"(r[1]), "=r"(r[2]), "=r"(r[3]) : "r"(addr));
}
__device__ __forceinline__ void mma_bf16(float* c, const uint32_t* a, uint32_t b0, uint32_t b1) {
    asm volatile(
        "mma.sync.aligned.m16n8k16.row.col.f32.bf16.bf16.f32 "
        "{%0,%1,%2,%3}, {%4,%5,%6,%7}, {%8,%9}, {%0,%1,%2,%3};"
        : "+f"(c[0]), "+f"(c[1]), "+f"(c[2]), "+f"(c[3])
        : "r"(a[0]), "r"(a[1]), "r"(a[2]), "r"(a[3]), "r"(b0), "r"(b1));
}
__device__ __forceinline__ uint32_t swz(uint32_t off) { return off ^ ((off >> 3) & 0x70); }

__device__ __forceinline__ uint16_t f2bf_bits(float x) {
    return __bfloat16_as_ushort(__float2bfloat16(x));
}
__device__ __forceinline__ float bf2f(uint16_t b) {
    return __bfloat162float(__ushort_as_bfloat16(b));
}

// ---------------------------------------------------------------------------
// split kernel: fp32 -> (hi, lo) bf16 pairs for z, T, Cw
// ---------------------------------------------------------------------------
__global__ void split_kernel(const float* __restrict__ z, const float* __restrict__ T,
                             const float* __restrict__ Cw) {
    const size_t gth = (size_t)blockIdx.x * blockDim.x + threadIdx.x;
    const size_t nth = (size_t)gridDim.x * blockDim.x;

    auto do_range = [&](const float* src, uint16_t* hi, uint16_t* lo, size_t n4) {
        for (size_t i = gth; i < n4; i += nth) {
            float4 v = ((const float4*)src)[i];
            uint16_t h0 = f2bf_bits(v.x), h1 = f2bf_bits(v.y);
            uint16_t h2 = f2bf_bits(v.z), h3 = f2bf_bits(v.w);
            uint16_t l0 = f2bf_bits(v.x - bf2f(h0));
            uint16_t l1 = f2bf_bits(v.y - bf2f(h1));
            uint16_t l2 = f2bf_bits(v.z - bf2f(h2));
            uint16_t l3 = f2bf_bits(v.w - bf2f(h3));
            ((uint2*)hi)[i] = make_uint2((uint32_t)h0 | ((uint32_t)h1 << 16),
                                         (uint32_t)h2 | ((uint32_t)h3 << 16));
            ((uint2*)lo)[i] = make_uint2((uint32_t)l0 | ((uint32_t)l1 << 16),
                                         (uint32_t)l2 | ((uint32_t)l3 << 16));
        }
    };
    do_range(z,  g_z_hi,  g_z_lo,  (size_t)NN * DD / 4);
    do_range(T,  g_T_hi,  g_T_lo,  (size_t)DEG * KK * DD / 4);
    do_range(Cw, g_Cw_hi, g_Cw_lo, (size_t)OO * KK / 4);
}

// ---------------------------------------------------------------------------
// Shared MMA-core: one chunk = [128 x 64] A x [128 x 64] B^T -> accumulate.
// Stage layout (64 KB): A_HI 0, A_LO 16K, B_HI 32K, B_LO 48K. 3 stages.
// 8 warps: wr = (wid&3)*32, wc = (wid>>2)*64 -> warp tile 32x64.
// ---------------------------------------------------------------------------
#define ST_AH 0
#define ST_AL 16384
#define ST_BH 32768
#define ST_BL 49152
#define ST_BYTES 65536
#define NSTAGE 3
#define MBAR_OFF (NSTAGE * ST_BYTES)                 // 196608: full[3] then empty[3]
#define EMPTY_OFF (MBAR_OFF + NSTAGE * 8)
#define GSMEM (EMPTY_OFF + NSTAGE * 8 + 16)

__device__ __forceinline__ void compute_chunk(uint32_t st, float acc[2][8][4],
                                              int wr, int wc, int lane) {
    const int l15 = lane & 15;
    const int lk  = (lane >> 4) << 4;      // 0 or 16 bytes
    #pragma unroll
    for (int ks = 0; ks < 4; ks++) {
        const uint32_t kb = ks * 32 + lk;
        uint32_t ah[2][4], al[2][4];
        #pragma unroll
        for (int mt = 0; mt < 2; mt++)
            ldsm4(ah[mt], st + ST_AH + swz((uint32_t)(wr + mt * 16 + l15) * 128 + kb));
        #pragma unroll
        for (int mt = 0; mt < 2; mt++)
            ldsm4(al[mt], st + ST_AL + swz((uint32_t)(wr + mt * 16 + l15) * 128 + kb));
        #pragma unroll
        for (int ng = 0; ng < 4; ng++) {
            uint32_t bh[4], bl[4];
            ldsm4(bh, st + ST_BH + swz((uint32_t)(wc + ng * 16 + l15) * 128 + kb));
            #pragma unroll
            for (int mt = 0; mt < 2; mt++) {      // hi*hi
                mma_bf16(acc[mt][2 * ng],     ah[mt], bh[0], bh[2]);
                mma_bf16(acc[mt][2 * ng + 1], ah[mt], bh[1], bh[3]);
            }
            #pragma unroll
            for (int mt = 0; mt < 2; mt++) {      // lo*hi
                mma_bf16(acc[mt][2 * ng],     al[mt], bh[0], bh[2]);
                mma_bf16(acc[mt][2 * ng + 1], al[mt], bh[1], bh[3]);
            }
            ldsm4(bl, st + ST_BL + swz((uint32_t)(wc + ng * 16 + l15) * 128 + kb));
            #pragma unroll
            for (int mt = 0; mt < 2; mt++) {      // hi*lo
                mma_bf16(acc[mt][2 * ng],     ah[mt], bl[0], bl[2]);
                mma_bf16(acc[mt][2 * ng + 1], ah[mt], bl[1], bl[3]);
            }
        }
    }
}

// ---------------------------------------------------------------------------
// poly kernel: persistent CTAs, continuous chunk stream across tiles,
// producer/consumer mbarriers (no per-chunk __syncthreads).
// Tile t (0..1023): k0 = (t&1)*128, row0 = (t>>1)*128. 64 chunks per tile.
// ---------------------------------------------------------------------------
__global__ void __launch_bounds__(NTHR, 1)
poly_mma_kernel(const float* __restrict__ T0,
                const __grid_constant__ CUtensorMap mZH,
                const __grid_constant__ CUtensorMap mZL,
                const __grid_constant__ CUtensorMap mTH,
                const __grid_constant__ CUtensorMap mTL) {
    extern __shared__ char smem[];
    const uint32_t sbase = smem_u32(smem);

    const int tid  = threadIdx.x;
    const int lane = tid & 31;
    const int wid  = tid >> 5;
    const int wr   = (wid & 3) * 32;   // warp row base
    const int wc   = (wid >> 2) * 64;  // warp col base
    const int rb   = wr + (lane >> 2);
    const int cb   = wc + 2 * (lane & 3);
    const int bid  = blockIdx.x;
    const int P    = gridDim.x;

    const int NTILE = 2 * (NN / 128);          // 1024
    const int NT = (NTILE - bid + P - 1) / P;  // my tile count
    const int S  = NT * 64;                    // my chunk-stream length

    if (tid == 0) {
        #pragma unroll
        for (int s2 = 0; s2 < NSTAGE; s2++) {
            mbar_init(sbase + MBAR_OFF  + s2 * 8, 1);
            mbar_init(sbase + EMPTY_OFF + s2 * 8, 8);
        }
        FENCE_PROXY();
    }
    __syncthreads();

    // stream index -> TMA coords
    auto prefetch = [&](int s) {   // caller: tid==0, s < S
        const int sti = s % NSTAGE;
        const int t   = bid + (s >> 6) * P;
        const int gi  = s & 63;
        const int d0  = (gi & 7) << 6;
        const int yA  = (t >> 1) << 7;                       // row0
        const int yB  = (gi >> 3) * KK + ((t & 1) << 7);     // nd*KK + k0
        if (s >= NSTAGE)
            mbar_wait(sbase + EMPTY_OFF + sti * 8, ((s / NSTAGE) - 1) & 1);
        const uint32_t st = sbase + sti * ST_BYTES;
        const uint32_t mb = sbase + MBAR_OFF + sti * 8;
        mbar_expect_tx(mb, 4 * 16384);
        tma2d(st + ST_AH, &mZH, d0, yA, mb);
        tma2d(st + ST_AL, &mZL, d0, yA, mb);
        tma2d(st + ST_BH, &mTH, d0, yB, mb);
        tma2d(st + ST_BL, &mTL, d0, yB, mb);
    };

    if (tid == 0) { prefetch(0); if (S > 1) prefetch(1); }

    float acc[2][8][4], p1[2][8][4], p2[2][8][4];
    int s = 0;

    for (int w = 0; w < NT; w++) {
        const int t    = bid + w * P;
        const int k0   = (t & 1) << 7;
        const int row0 = (t >> 1) << 7;

        // p2 init = T0[k] broadcast over rows (degree 0)
        #pragma unroll
        for (int nt = 0; nt < 8; nt++) {
            float t0 = __ldg(&T0[k0 + cb + nt * 8]);
            float t1 = __ldg(&T0[k0 + cb + nt * 8 + 1]);
            #pragma unroll
            for (int mt = 0; mt < 2; mt++) {
                p2[mt][nt][0] = t0; p2[mt][nt][1] = t1;
                p2[mt][nt][2] = t0; p2[mt][nt][3] = t1;
            }
        }

        for (int n = 1; n <= DEG; n++) {
            #pragma unroll
            for (int mt = 0; mt < 2; mt++)
                #pragma unroll
                for (int nt = 0; nt < 8; nt++)
                    #pragma unroll
                    for (int f = 0; f < 4; f++) acc[mt][nt][f] = 0.0f;

            for (int j = 0; j < 8; j++) {
                const int sti = s % NSTAGE;
                mbar_wait(sbase + MBAR_OFF + sti * 8, (s / NSTAGE) & 1);
                if (tid == 0 && s + 2 < S) prefetch(s + 2);
                compute_chunk(sbase + sti * ST_BYTES, acc, wr, wc, lane);
                if (lane == 0) mbar_arrive(sbase + EMPTY_OFF + sti * 8);
                s++;
            }

            // ---- recurrence epilogue (pure registers) ----
            const float fa = (2.0f * n - 1.0f) / n;
            const float fb = (n - 1.0f) / n;
            if (n == 1) {
                #pragma unroll
                for (int mt = 0; mt < 2; mt++)
                    #pragma unroll
                    for (int nt = 0; nt < 8; nt++)
                        #pragma unroll
                        for (int f = 0; f < 4; f++) p1[mt][nt][f] = acc[mt][nt][f];
            } else if (n < DEG) {
                #pragma unroll
                for (int mt = 0; mt < 2; mt++)
                    #pragma unroll
                    for (int nt = 0; nt < 8; nt++)
                        #pragma unroll
                        for (int f = 0; f < 4; f++) {
                            float cur = fa * acc[mt][nt][f] * p1[mt][nt][f] - fb * p2[mt][nt][f];
                            p2[mt][nt][f] = p1[mt][nt][f];
                            p1[mt][nt][f] = cur;
                        }
            } else {
                // n == 8: cur -> out8 split bf16 hi/lo, direct to gmem
                #pragma unroll
                for (int mt = 0; mt < 2; mt++)
                    #pragma unroll
                    for (int nt = 0; nt < 8; nt++)
                        #pragma unroll
                        for (int h = 0; h < 2; h++) {
                            const int r = rb + mt * 16 + h * 8;
                            const int c = cb + nt * 8;
                            float c0 = fa * acc[mt][nt][2 * h]     * p1[mt][nt][2 * h]
                                     - fb * p2[mt][nt][2 * h];
                            float c1 = fa * acc[mt][nt][2 * h + 1] * p1[mt][nt][2 * h + 1]
                                     - fb * p2[mt][nt][2 * h + 1];
                            uint16_t h0 = f2bf_bits(c0), h1 = f2bf_bits(c1);
                            uint16_t l0 = f2bf_bits(c0 - bf2f(h0));
                            uint16_t l1 = f2bf_bits(c1 - bf2f(h1));
                            size_t idx = (size_t)(row0 + r) * KK + k0 + c;
                            *(uint32_t*)&g_o8_hi[idx] = (uint32_t)h0 | ((uint32_t)h1 << 16);
                            *(uint32_t*)&g_o8_lo[idx] = (uint32_t)l0 | ((uint32_t)l1 << 16);
                        }
            }
        }
    }
}

// ---------------------------------------------------------------------------
// C kernel: out[N,512] = out8[N,256] @ Cw^T + Cb  (persistent, continuous)
// Tile t (0..2047): o0 = (t&3)*128, row0 = (t>>2)*128. 4 chunks per tile.
// ---------------------------------------------------------------------------
__global__ void __launch_bounds__(NTHR, 1)
cgemm_mma_kernel(const float* __restrict__ Cb, float* __restrict__ out,
                 const __grid_constant__ CUtensorMap mOH,
                 const __grid_constant__ CUtensorMap mOL,
                 const __grid_constant__ CUtensorMap mCH,
                 const __grid_constant__ CUtensorMap mCL) {
    extern __shared__ char smem[];
    const uint32_t sbase = smem_u32(smem);

    const int tid  = threadIdx.x;
    const int lane = tid & 31;
    const int wid  = tid >> 5;
    const int wr   = (wid & 3) * 32;
    const int wc   = (wid >> 2) * 64;
    const int bid  = blockIdx.x;
    const int P    = gridDim.x;

    const int NTILE = 4 * (NN / 128);          // 2048
    const int NT = (NTILE - bid + P - 1) / P;
    const int S  = NT * 4;

    if (tid == 0) {
        #pragma unroll
        for (int s2 = 0; s2 < NSTAGE; s2++) {
            mbar_init(sbase + MBAR_OFF  + s2 * 8, 1);
            mbar_init(sbase + EMPTY_OFF + s2 * 8, 8);
        }
        FENCE_PROXY();
    }
    __syncthreads();

    auto prefetch = [&](int s) {
        const int sti = s % NSTAGE;
        const int t   = bid + (s >> 2) * P;
        const int d0  = (s & 3) << 6;
        const int yA  = (t >> 2) << 7;        // row0
        const int yB  = (t & 3) << 7;         // o0
        if (s >= NSTAGE)
            mbar_wait(sbase + EMPTY_OFF + sti * 8, ((s / NSTAGE) - 1) & 1);
        const uint32_t st = sbase + sti * ST_BYTES;
        const uint32_t mb = sbase + MBAR_OFF + sti * 8;
        mbar_expect_tx(mb, 4 * 16384);
        tma2d(st + ST_AH, &mOH, d0, yA, mb);
        tma2d(st + ST_AL, &mOL, d0, yA, mb);
        tma2d(st + ST_BH, &mCH, d0, yB, mb);
        tma2d(st + ST_BL, &mCL, d0, yB, mb);
    };

    if (tid == 0) { prefetch(0); if (S > 1) prefetch(1); }

    float acc[2][8][4];
    int s = 0;
    const int rb = wr + (lane >> 2);
    const int cb = wc + 2 * (lane & 3);

    for (int w = 0; w < NT; w++) {
        const int t    = bid + w * P;
        const int o0   = (t & 3) << 7;
        const int row0 = (t >> 2) << 7;

        #pragma unroll
        for (int mt = 0; mt < 2; mt++)
            #pragma unroll
            for (int nt = 0; nt < 8; nt++)
                #pragma unroll
                for (int f = 0; f < 4; f++) acc[mt][nt][f] = 0.0f;

        for (int j = 0; j < 4; j++) {
            const int sti = s % NSTAGE;
            mbar_wait(sbase + MBAR_OFF + sti * 8, (s / NSTAGE) & 1);
            if (tid == 0 && s + 2 < S) prefetch(s + 2);
            compute_chunk(sbase + sti * ST_BYTES, acc, wr, wc, lane);
            if (lane == 0) mbar_arrive(sbase + EMPTY_OFF + sti * 8);
            s++;
        }

        #pragma unroll
        for (int nt = 0; nt < 8; nt++) {
            const int c = o0 + cb + nt * 8;
            float2 bias = *(const float2*)&Cb[c];
            #pragma unroll
            for (int mt = 0; mt < 2; mt++)
                #pragma unroll
                for (int h = 0; h < 2; h++) {
                    const int r = row0 + rb + mt * 16 + h * 8;
                    float2 v = make_float2(acc[mt][nt][2 * h] + bias.x,
                                           acc[mt][nt][2 * h + 1] + bias.y);
                    *(float2*)&out[(size_t)r * OO + c] = v;
                }
        }
    }
}

// ---------------------------------------------------------------------------
// Host: build tensormaps (driver API via dlopen), persistent launches.
// ---------------------------------------------------------------------------
typedef decltype(&cuTensorMapEncodeTiled) EncodeFn;

static void enc2d(EncodeFn fn, CUtensorMap* m, void* base,
                  uint64_t d0, uint64_t d1, uint64_t stride_bytes) {
    cuuint64_t gd[2] = {d0, d1};
    cuuint64_t gs[1] = {stride_bytes};
    cuuint32_t box[2] = {64, 128};
    cuuint32_t es[2] = {1, 1};
    fn(m, CU_TENSOR_MAP_DATA_TYPE_BFLOAT16, 2, base, gd, gs, box, es,
       CU_TENSOR_MAP_INTERLEAVE_NONE, CU_TENSOR_MAP_SWIZZLE_128B,
       CU_TENSOR_MAP_L2_PROMOTION_L2_128B, CU_TENSOR_MAP_FLOAT_OOB_FILL_NONE);
}

extern "C" void kernel_launch(void* const* d_in, const int* in_sizes, int n_in,
                              void* d_out, int out_size) {
    const float* z  = (const float*)d_in[0];
    const float* T0 = (const float*)d_in[1];
    const float* T  = (const float*)d_in[2];
    const float* Cw = (const float*)d_in[3];
    const float* Cb = (const float*)d_in[4];
    float* out = (float*)d_out;

    void* h = dlopen("libcuda.so.1", RTLD_NOW | RTLD_GLOBAL);
    EncodeFn fn = (EncodeFn)dlsym(h, "cuTensorMapEncodeTiled");

    void *p_zh, *p_zl, *p_th, *p_tl, *p_ch, *p_cl, *p_oh, *p_ol;
    cudaGetSymbolAddress(&p_zh, g_z_hi);
    cudaGetSymbolAddress(&p_zl, g_z_lo);
    cudaGetSymbolAddress(&p_th, g_T_hi);
    cudaGetSymbolAddress(&p_tl, g_T_lo);
    cudaGetSymbolAddress(&p_ch, g_Cw_hi);
    cudaGetSymbolAddress(&p_cl, g_Cw_lo);
    cudaGetSymbolAddress(&p_oh, g_o8_hi);
    cudaGetSymbolAddress(&p_ol, g_o8_lo);

    CUtensorMap mZH, mZL, mTH, mTL, mOH, mOL, mCH, mCL;
    enc2d(fn, &mZH, p_zh, DD, NN,       DD * 2);
    enc2d(fn, &mZL, p_zl, DD, NN,       DD * 2);
    enc2d(fn, &mTH, p_th, DD, DEG * KK, DD * 2);
    enc2d(fn, &mTL, p_tl, DD, DEG * KK, DD * 2);
    enc2d(fn, &mOH, p_oh, KK, NN,       KK * 2);
    enc2d(fn, &mOL, p_ol, KK, NN,       KK * 2);
    enc2d(fn, &mCH, p_ch, KK, OO,       KK * 2);
    enc2d(fn, &mCL, p_cl, KK, OO,       KK * 2);

    int nsm = 148, dev = 0;
    cudaGetDevice(&dev);
    cudaDeviceGetAttribute(&nsm, cudaDevAttrMultiProcessorCount, dev);

    cudaFuncSetAttribute(poly_mma_kernel,  cudaFuncAttributeMaxDynamicSharedMemorySize, GSMEM);
    cudaFuncSetAttribute(cgemm_mma_kernel, cudaFuncAttributeMaxDynamicSharedMemorySize, GSMEM);

    split_kernel<<<2048, STHR>>>(z, T, Cw);
    poly_mma_kernel<<<nsm, NTHR, GSMEM>>>(T0, mZH, mZL, mTH, mTL);
    cgemm_mma_kernel<<<nsm, NTHR, GSMEM>>>(Cb, out, mOH, mOL, mCH, mCL);
}